// round 13
// baseline (speedup 1.0000x reference)
#include <cuda_runtime.h>
#include <math.h>

#define N_BINS 1024
#define NMASK  (N_BINS - 1)
#define DIM    512
#define DIM4   128            // DIM / 4 (float4 units)
#define NSTEPS 240
#define NK     122            // lags k in [-61, 60]
#define TI     8              // bins per block
#define NBLK   (N_BINS / TI)  // 128 blocks
#define NTHREADS 768
#define NWARPS   24
#define ROWS_PER_WARP 6       // window rows 0..128 covered by warps 0..21
#define STAG_W   512          // float4 per warp: 2 bufs x 2 rows x 128
#define DYN_BYTES (NWARPS * STAG_W * 16)   // 196608 B dynamic smem

// Scratch (device globals; no allocations allowed)
__device__ float g_bpart[NSTEPS * NBLK];   // per-(step, block) partial sums
__device__ unsigned g_ticket;              // last-block election (reset each launch)

union F4U2 { float4 f4; unsigned long long u[2]; };

__device__ __forceinline__ unsigned long long fma2(unsigned long long a,
                                                   unsigned long long b,
                                                   unsigned long long c) {
    unsigned long long d;
    asm("fma.rn.f32x2 %0, %1, %2, %3;" : "=l"(d) : "l"(a), "l"(b), "l"(c));
    return d;
}
__device__ __forceinline__ unsigned long long dot4x2(const F4U2& x, const F4U2& y,
                                                     unsigned long long acc) {
    acc = fma2(x.u[0], y.u[0], acc);
    acc = fma2(x.u[1], y.u[1], acc);
    return acc;
}
__device__ __forceinline__ float unpack_sum(unsigned long long v) {
    return __uint_as_float((unsigned)(v & 0xffffffffull))
         + __uint_as_float((unsigned)(v >> 32));
}
__device__ __forceinline__ float dot4(float4 a, float4 b) {
    return a.x * b.x + a.y * b.y + a.z * b.z + a.w * b.w;
}
__device__ __forceinline__ void cp16(unsigned dst, const float4* src) {
    asm volatile("cp.async.cg.shared.global [%0], [%1], 16;" :: "r"(dst), "l"(src));
}
#define CP_COMMIT() asm volatile("cp.async.commit_group;")
#define CP_WAIT(n)  asm volatile("cp.async.wait_group %0;" :: "n"(n))

// ---------------------------------------------------------------------------
// k_main: one block per 8-bin tile (R4/R11/R12 structure; cp.async staging).
//   Phase 1: load 8 D_p rows to smem, compute |P|^2 per bin.
//   Phase 2: per-warp double-buffered cp.async staging of Q rows; 2-row
//            batches, barrier-free, packed-f32x2 dots; LDG latency off the
//            serial path.
//   Phase 3: evaluate all 240 fractional steps, emit per-block partial sums.
//   Phase 4: last block (atomic ticket) -> mean dist -> argmin -> out.
// ---------------------------------------------------------------------------
__global__ void __launch_bounds__(NTHREADS) k_main(const float* __restrict__ Dq,
                                                   const float* __restrict__ Dp,
                                                   float* __restrict__ out) {
    extern __shared__ __align__(16) float4 dynstag[];   // [24][2][2][128]
    __shared__ float4 Ps[TI][DIM4];  // 16 KB
    __shared__ float  Xs[TI][128];   // 4 KB, index kk = k + 61 in [0,121]
    __shared__ float  sQ2[136];      // window rows 0..128 used
    __shared__ float  sA[136];
    __shared__ float  sP2[TI];

    const int i0   = blockIdx.x * TI;
    const int tid  = threadIdx.x;
    const int warp = tid >> 5;
    const int lane = tid & 31;

    const float4* P4 = (const float4*)Dp;
    const float4* Q4 = (const float4*)Dq;

    const int base = ROWS_PER_WARP * warp;
    const bool wactive = (base <= 128);           // warps 22,23 idle in phase 2

    float4* stag = dynstag + warp * STAG_W;       // this warp's staging
    const unsigned sbw =
        (unsigned)__cvta_generic_to_shared(stag); // byte address of staging

    // issue cp.async for batch mm (rows base+2mm, base+2mm+1) into buf mm&1
    auto issue_batch = [&](int mm) {
        const int ra = base + 2 * mm;
        const int ja = (i0 - 60 + ra) & NMASK;
        const int jb = (i0 - 60 + ra + 1) & NMASK;
        const unsigned dstA = sbw + (unsigned)((mm & 1) * 256) * 16u;
        const unsigned dstB = dstA + 128u * 16u;
        #pragma unroll
        for (int k = 0; k < 4; k++) {
            cp16(dstA + (lane + 32 * k) * 16u, Q4 + ja * DIM4 + lane + 32 * k);
            cp16(dstB + (lane + 32 * k) * 16u, Q4 + jb * DIM4 + lane + 32 * k);
        }
        CP_COMMIT();
    };

    // ---- prologue: stage batches 0 and 1; seed prev-row via LDG ----------
    F4U2 pv0, pv1, pv2, pv3;
    if (wactive) {
        issue_batch(0);
        issue_batch(1);
        const float4* qp = Q4 + (((i0 - 61 + base) & NMASK) * DIM4);  // row base-1
        pv0.f4 = qp[lane]; pv1.f4 = qp[lane + 32];
        pv2.f4 = qp[lane + 64]; pv3.f4 = qp[lane + 96];
    }

    // ---- Phase 1: P rows to smem (overlaps staged loads) -----------------
    for (int idx = tid; idx < TI * DIM4; idx += NTHREADS) {
        int t = idx >> 7, c = idx & 127;
        Ps[t][c] = P4[(i0 + t) * DIM4 + c];
    }
    __syncthreads();

    if (warp < TI) {  // warp w -> |P[i0+w]|^2
        float4 p0 = Ps[warp][lane], p1 = Ps[warp][lane + 32],
               p2 = Ps[warp][lane + 64], p3 = Ps[warp][lane + 96];
        float s = dot4(p0, p0) + dot4(p1, p1) + dot4(p2, p2) + dot4(p3, p3);
        #pragma unroll
        for (int off = 16; off; off >>= 1) s += __shfl_xor_sync(0xffffffffu, s, off);
        if (lane == 0) sP2[warp] = s;
    }

    // ---- Phase 2: staged Q streaming (barrier-free) ----------------------
    if (wactive) {
        #pragma unroll
        for (int m = 0; m < 3; m++) {
            if (m < 2) { CP_WAIT(1); } else { CP_WAIT(0); }   // batch m arrived

            const float4* sa = stag + (m & 1) * 256;   // row ra
            const float4* sb = sa + 128;               // row rb
            F4U2 a0, a1, a2, a3, b0, b1, b2, b3;
            a0.f4 = sa[lane]; a1.f4 = sa[lane + 32];
            a2.f4 = sa[lane + 64]; a3.f4 = sa[lane + 96];
            b0.f4 = sb[lane]; b1.f4 = sb[lane + 32];
            b2.f4 = sb[lane + 64]; b3.f4 = sb[lane + 96];

            // refill just-read buffer for batch m+2 (writes land >=300cyc
            // after issue; rows are already register-resident)
            if (m == 0) issue_batch(2);

            const int ra = base + 2 * m;
            const int rb = ra + 1;

            // stats (packed): |a|^2, |b|^2, a.prev, b.a
            float q2a, q2b, aa, ab;
            {
                unsigned long long s;
                s = dot4x2(a0, a0, 0ull); s = dot4x2(a1, a1, s);
                s = dot4x2(a2, a2, s);    s = dot4x2(a3, a3, s);
                q2a = unpack_sum(s);
                s = dot4x2(b0, b0, 0ull); s = dot4x2(b1, b1, s);
                s = dot4x2(b2, b2, s);    s = dot4x2(b3, b3, s);
                q2b = unpack_sum(s);
                s = dot4x2(a0, pv0, 0ull); s = dot4x2(a1, pv1, s);
                s = dot4x2(a2, pv2, s);    s = dot4x2(a3, pv3, s);
                aa = unpack_sum(s);
                s = dot4x2(b0, a0, 0ull); s = dot4x2(b1, a1, s);
                s = dot4x2(b2, a2, s);    s = dot4x2(b3, a3, s);
                ab = unpack_sum(s);
            }

            // cross-corr: v[2t] = a.P[t], v[2t+1] = b.P[t]  (packed)
            float v[2 * TI];
            #pragma unroll
            for (int t = 0; t < TI; t++) {
                F4U2 p0, p1, p2, p3;
                p0.f4 = Ps[t][lane];      p1.f4 = Ps[t][lane + 32];
                p2.f4 = Ps[t][lane + 64]; p3.f4 = Ps[t][lane + 96];
                unsigned long long va, vb;
                va = dot4x2(a0, p0, 0ull); va = dot4x2(a1, p1, va);
                va = dot4x2(a2, p2, va);   va = dot4x2(a3, p3, va);
                vb = dot4x2(b0, p0, 0ull); vb = dot4x2(b1, p1, vb);
                vb = dot4x2(b2, p2, vb);   vb = dot4x2(b3, p3, vb);
                v[2 * t]     = unpack_sum(va);
                v[2 * t + 1] = unpack_sum(vb);
            }

            // ---- folded multi-array reduction: 16 arrays over 32 lanes.
            float r8[8];
            #pragma unroll
            for (int i = 0; i < 8; i++) {
                bool hi = (lane & 16) != 0;
                float mine  = hi ? v[2 * i + 1] : v[2 * i];
                float other = hi ? v[2 * i]     : v[2 * i + 1];
                r8[i] = mine + __shfl_xor_sync(0xffffffffu, other, 16);
            }
            float r4[4];
            #pragma unroll
            for (int i = 0; i < 4; i++) {
                bool hi = (lane & 8) != 0;
                float mine  = hi ? r8[2 * i + 1] : r8[2 * i];
                float other = hi ? r8[2 * i]     : r8[2 * i + 1];
                r4[i] = mine + __shfl_xor_sync(0xffffffffu, other, 8);
            }
            float r2a[2];
            #pragma unroll
            for (int i = 0; i < 2; i++) {
                bool hi = (lane & 4) != 0;
                float mine  = hi ? r4[2 * i + 1] : r4[2 * i];
                float other = hi ? r4[2 * i]     : r4[2 * i + 1];
                r2a[i] = mine + __shfl_xor_sync(0xffffffffu, other, 4);
            }
            float r1;
            {
                bool hi = (lane & 2) != 0;
                float mine  = hi ? r2a[1] : r2a[0];
                float other = hi ? r2a[0] : r2a[1];
                r1 = mine + __shfl_xor_sync(0xffffffffu, other, 2);
            }
            r1 += __shfl_xor_sync(0xffffffffu, r1, 1);
            if (!(lane & 1)) {
                int g   = ((lane >> 4) & 1) | (((lane >> 3) & 1) << 1)
                        | (((lane >> 2) & 1) << 2) | (((lane >> 1) & 1) << 3);
                int t   = g >> 1;
                int row = (g & 1) ? rb : ra;
                int kk  = t + 121 - row;   // k + 61  (rows > 128 -> kk < 0)
                if (kk >= 0 && kk < NK) Xs[t][kk] = r1;
            }

            // ---- stats reduction: 4 arrays (q2a,q2b,aa,ab)
            float s1;
            {
                bool hi = (lane & 16) != 0;
                float m0 = hi ? q2b : q2a, o0 = hi ? q2a : q2b;
                float m1 = hi ? ab  : aa,  o1 = hi ? aa  : ab;
                float u0 = m0 + __shfl_xor_sync(0xffffffffu, o0, 16);
                float u1 = m1 + __shfl_xor_sync(0xffffffffu, o1, 16);
                bool h2 = (lane & 8) != 0;
                float mm = h2 ? u1 : u0, oo = h2 ? u0 : u1;
                s1 = mm + __shfl_xor_sync(0xffffffffu, oo, 8);
            }
            s1 += __shfl_xor_sync(0xffffffffu, s1, 4);
            s1 += __shfl_xor_sync(0xffffffffu, s1, 2);
            s1 += __shfl_xor_sync(0xffffffffu, s1, 1);
            if (lane == 0  && ra <= 128) sQ2[ra] = s1;
            if (lane == 16 && rb <= 128) sQ2[rb] = s1;
            if (lane == 8  && ra <= 128) sA[ra]  = s1;
            if (lane == 24 && rb <= 128) sA[rb]  = s1;

            pv0 = b0; pv1 = b1; pv2 = b2; pv3 = b3;
        }
    }
    __syncthreads();

    // ---- Phase 3: evaluate 240 steps over this block's 8 bins ----------
    if (tid < NSTEPS) {
        const int s = tid;
        int k0, k1; float alpha; bool pos;
        if (s < 120) {                         // steps 0.0, 0.5, ..., 59.5
            k0 = s >> 1; k1 = k0 + 1;
            alpha = (s & 1) ? 0.5f : 0.0f;
            pos = true;
        } else {                               // steps -1.0, -1.5, ..., -60.5
            int u = s - 120;
            k0 = -(1 + (u >> 1)); k1 = k0 - 1;
            alpha = (u & 1) ? 0.5f : 0.0f;
            pos = false;
        }
        const float w0 = 1.0f - alpha, w1 = alpha;
        const float w00 = w0 * w0, w11 = w1 * w1, w01 = 2.0f * w0 * w1;
        float acc = 0.0f;
        #pragma unroll
        for (int t = 0; t < TI; t++) {
            int j0r = t + 60 - k0;             // window-relative row of roll k0
            int j1r = t + 60 - k1;
            float adot = pos ? sA[j0r] : sA[j1r];   // Q[j0].Q[j1] adjacency
            float x0 = Xs[t][k0 + 61];
            float x1 = Xs[t][k1 + 61];
            float r2 = sP2[t] + w00 * sQ2[j0r] + w11 * sQ2[j1r]
                     + w01 * adot - 2.0f * (w0 * x0 + w1 * x1);
            acc += sqrtf(fmaxf(r2, 0.0f));
        }
        g_bpart[s * NBLK + blockIdx.x] = acc;
    }

    // ---- Phase 4: last block reduces everything (no second launch) -----
    __threadfence();
    __shared__ bool is_last;
    __syncthreads();                 // all phase-3 stores of this block issued
    if (tid == 0) {
        unsigned t = atomicAdd(&g_ticket, 1u);
        is_last = (t == (unsigned)(NBLK - 1));
        if (is_last) g_ticket = 0;   // reset for next graph replay
    }
    __syncthreads();
    if (!is_last) return;

    // Deterministic mean + argmin (identical summation order every launch).
    const int s    = tid >> 1;       // 2 threads per step, 64 partials each
    const int half = tid & 1;
    unsigned long long key = ~0ull;
    if (s < NSTEPS) {
        const float4* bp = (const float4*)(g_bpart + s * NBLK + half * (NBLK / 2));
        float s0 = 0.f, s1 = 0.f, s2 = 0.f, s3 = 0.f;
        #pragma unroll
        for (int c = 0; c < NBLK / 8; c += 4) {
            float4 v0 = bp[c], v1 = bp[c + 1], v2 = bp[c + 2], v3 = bp[c + 3];
            s0 += v0.x + v0.y + v0.z + v0.w;
            s1 += v1.x + v1.y + v1.z + v1.w;
            s2 += v2.x + v2.y + v2.z + v2.w;
            s3 += v3.x + v3.y + v3.z + v3.w;
        }
        float mine = (s0 + s1) + (s2 + s3);
        float tot  = mine + __shfl_xor_sync(0xffffffffu, mine, 1);
        float dist = tot * (1.0f / (float)N_BINS);
        // positive-float bit order == numeric order; low 32 bits = index so
        // ties resolve to the smallest step index (matches jnp.argmin).
        key = ((unsigned long long)__float_as_uint(dist) << 32) | (unsigned)s;
    }
    #pragma unroll
    for (int off = 16; off; off >>= 1) {
        unsigned long long o = __shfl_xor_sync(0xffffffffu, key, off);
        if (o < key) key = o;
    }
    __shared__ unsigned long long wk[NWARPS];
    if (lane == 0) wk[warp] = key;
    __syncthreads();
    if (tid == 0) {
        unsigned long long best = wk[0];
        #pragma unroll
        for (int w = 1; w < NWARPS; w++) if (wk[w] < best) best = wk[w];
        int bi = (int)(best & 0xffffffffull);
        float dist = __uint_as_float((unsigned)(best >> 32));
        float step = (bi < 120) ? 0.5f * (float)bi : -(1.0f + 0.5f * (float)(bi - 120));
        out[0] = step;
        out[1] = dist;
    }
}

extern "C" void kernel_launch(void* const* d_in, const int* in_sizes, int n_in,
                              void* d_out, int out_size) {
    const float* Dq = (const float*)d_in[0];  // D_q [1024, 512]
    const float* Dp = (const float*)d_in[1];  // D_p [1024, 512]
    float* out = (float*)d_out;

    cudaFuncSetAttribute(k_main, cudaFuncAttributeMaxDynamicSharedMemorySize,
                         DYN_BYTES);
    k_main<<<NBLK, NTHREADS, DYN_BYTES>>>(Dq, Dp, out);
}